// round 4
// baseline (speedup 1.0000x reference)
#include <cuda_runtime.h>
#include <cuda_bf16.h>
#include <cstdint>

#define NN  100000
#define EE  1200000
#define FIN 128
#define HID 64

// Scratch (static __device__ arrays — no allocation allowed)
__device__ __align__(256) float g_ys [(size_t)NN * HID];   // dinv-scaled features (gather source)
__device__ __align__(256) float g_acc[(size_t)NN * HID];   // aggregation result
__device__ __align__(256) float g_dinv[NN];
__device__ __align__(256) int   g_cnt[NN];
__device__ __align__(256) int   g_off[NN + 1];
__device__ __align__(256) int   g_cur[NN];
__device__ __align__(256) int   g_srcs[EE];                // dst-sorted source ids (CSR)
__device__ __align__(256) float g_s1[NN];                  // scalar layer source
__device__ __align__(256) float g_s2[NN];                  // scalar layer result
__device__ int g_is64;

// ---------- edge dtype detection (int64 vs silently-demoted int32) ----------
__global__ void k_detect(const long long* ei, int e) {
    if (blockIdx.x == 0 && threadIdx.x == 0) {
        int ok = 1;
        int m = e < 64 ? e : 64;
        for (int i = 0; i < m; i++) {
            long long v = ei[i];
            if (v < 0 || v >= NN) { ok = 0; break; }
        }
        g_is64 = ok;
    }
}

__device__ __forceinline__ int edge_at(const void* ei, int is64, size_t idx) {
    if (is64) return (int)((const long long*)ei)[idx];
    return ((const int*)ei)[idx];
}

// ---------- CSR build: histogram -> scan -> fill ----------
__global__ void k_zero(int n) {
    int i = blockIdx.x * blockDim.x + threadIdx.x;
    if (i < n) g_cnt[i] = 0;
}

__global__ void k_count(const void* ei, int e) {
    int i = blockIdx.x * blockDim.x + threadIdx.x;
    if (i >= e) return;
    int is64 = g_is64;
    int dst = edge_at(ei, is64, (size_t)e + i);
    atomicAdd(&g_cnt[dst], 1);
}

// single block, 1024 threads: chunked exclusive scan; also emits dinv and cursor
__global__ __launch_bounds__(1024) void k_scan(int n) {
    __shared__ int sh[1024];
    int t = threadIdx.x;
    int chunk = (n + 1023) >> 10;
    int beg = t * chunk;
    int end = beg + chunk; if (end > n) end = n;
    int s = 0;
    for (int i = beg; i < end; i++) s += g_cnt[i];
    sh[t] = s;
    __syncthreads();
    // Hillis-Steele inclusive scan
    for (int d = 1; d < 1024; d <<= 1) {
        int v = (t >= d) ? sh[t - d] : 0;
        __syncthreads();
        sh[t] += v;
        __syncthreads();
    }
    int off = sh[t] - s;   // exclusive prefix
    for (int i = beg; i < end; i++) {
        int c = g_cnt[i];
        g_off[i] = off;
        g_cur[i] = off;
        g_dinv[i] = rsqrtf(1.0f + (float)c);   // +1 self loop
        off += c;
    }
    if (t == 1023) g_off[n] = sh[1023];
}

__global__ void k_fill(const void* ei, int e) {
    int i = blockIdx.x * blockDim.x + threadIdx.x;
    if (i >= e) return;
    int is64 = g_is64;
    int src = edge_at(ei, is64, (size_t)i);
    int dst = edge_at(ei, is64, (size_t)e + i);
    int pos = atomicAdd(&g_cur[dst], 1);
    g_srcs[pos] = src;
}

// ---------- tiled SGEMM: ys = (A @ W) * dinv ----------
// BM=128, BN=64, BK=16, 256 threads, per-thread 8x4 micro-tile.
// FUSE: A := relu(g_acc * dinv[row] + bias[k]) applied on the smem-load path.
template <int K, bool FUSE>
__global__ __launch_bounds__(256)
void k_gemm(const float* __restrict__ A, const float* __restrict__ W,
            const float* __restrict__ bias, int n) {
    constexpr int BM = 128, BN = 64, BK = 16;
    __shared__ float Ws[K * BN];       // whole W resident
    __shared__ float As[BK][BM];       // k-major A tile (transposed on load)

    int tid = threadIdx.x;
    for (int i = tid; i < (K * BN) / 4; i += 256)
        reinterpret_cast<float4*>(Ws)[i] = reinterpret_cast<const float4*>(W)[i];

    int tx = tid & 15;        // col group: 4 cols
    int ty = tid >> 4;        // row group: 8 rows
    int row0 = blockIdx.x * BM;

    float acc[8][4];
#pragma unroll
    for (int r = 0; r < 8; r++)
#pragma unroll
        for (int c = 0; c < 4; c++) acc[r][c] = 0.0f;

    const float* Asrc = FUSE ? g_acc : A;

    for (int k0 = 0; k0 < K; k0 += BK) {
        __syncthreads();
        // load+transpose A chunk: 512 float4 loads, 2 per thread
#pragma unroll
        for (int l = 0; l < 2; l++) {
            int lin = tid + l * 256;         // 0..511
            int row = lin & 127;
            int kq  = lin >> 7;              // 0..3
            int grow = row0 + row;
            float4 v = make_float4(0.f, 0.f, 0.f, 0.f);
            if (grow < n)
                v = *reinterpret_cast<const float4*>(Asrc + (size_t)grow * K + k0 + kq * 4);
            if (FUSE) {
                float di = (grow < n) ? g_dinv[grow] : 1.0f;
                v.x = fmaxf(fmaf(v.x, di, __ldg(&bias[k0 + kq * 4 + 0])), 0.0f);
                v.y = fmaxf(fmaf(v.y, di, __ldg(&bias[k0 + kq * 4 + 1])), 0.0f);
                v.z = fmaxf(fmaf(v.z, di, __ldg(&bias[k0 + kq * 4 + 2])), 0.0f);
                v.w = fmaxf(fmaf(v.w, di, __ldg(&bias[k0 + kq * 4 + 3])), 0.0f);
            }
            As[kq * 4 + 0][row] = v.x;
            As[kq * 4 + 1][row] = v.y;
            As[kq * 4 + 2][row] = v.z;
            As[kq * 4 + 3][row] = v.w;
        }
        __syncthreads();

#pragma unroll
        for (int k = 0; k < BK; k++) {
            float4 b  = *reinterpret_cast<const float4*>(&Ws[(k0 + k) * BN + tx * 4]);
            float4 a0 = *reinterpret_cast<const float4*>(&As[k][ty * 8]);
            float4 a1 = *reinterpret_cast<const float4*>(&As[k][ty * 8 + 4]);
            float a[8] = {a0.x, a0.y, a0.z, a0.w, a1.x, a1.y, a1.z, a1.w};
            float bb[4] = {b.x, b.y, b.z, b.w};
#pragma unroll
            for (int r = 0; r < 8; r++)
#pragma unroll
                for (int c = 0; c < 4; c++)
                    acc[r][c] = fmaf(a[r], bb[c], acc[r][c]);
        }
    }

    // epilogue: scale by dinv[row], write gather source
#pragma unroll
    for (int r = 0; r < 8; r++) {
        int grow = row0 + ty * 8 + r;
        if (grow < n) {
            float di = g_dinv[grow];
            float4 o = make_float4(acc[r][0] * di, acc[r][1] * di,
                                   acc[r][2] * di, acc[r][3] * di);
            *reinterpret_cast<float4*>(g_ys + (size_t)grow * HID + tx * 4) = o;
        }
    }
}

// ---------- CSR pull aggregation: acc[v] = ys[v] + sum_{u in N(v)} ys[u] ----------
// 16 threads per node, float4 per thread, 4-deep neighbor unroll for MLP.
__global__ void k_aggr(int n) {
    int t = blockIdx.x * blockDim.x + threadIdx.x;
    int node = t >> 4;
    if (node >= n) return;
    int part = t & 15;

    float4 acc = *reinterpret_cast<const float4*>(g_ys + (size_t)node * HID + part * 4);
    int j   = g_off[node];
    int end = g_off[node + 1];

    for (; j + 4 <= end; j += 4) {
        int s0 = g_srcs[j + 0], s1 = g_srcs[j + 1];
        int s2 = g_srcs[j + 2], s3 = g_srcs[j + 3];
        float4 v0 = *reinterpret_cast<const float4*>(g_ys + (size_t)s0 * HID + part * 4);
        float4 v1 = *reinterpret_cast<const float4*>(g_ys + (size_t)s1 * HID + part * 4);
        float4 v2 = *reinterpret_cast<const float4*>(g_ys + (size_t)s2 * HID + part * 4);
        float4 v3 = *reinterpret_cast<const float4*>(g_ys + (size_t)s3 * HID + part * 4);
        acc.x += v0.x + v1.x + v2.x + v3.x;
        acc.y += v0.y + v1.y + v2.y + v3.y;
        acc.z += v0.z + v1.z + v2.z + v3.z;
        acc.w += v0.w + v1.w + v2.w + v3.w;
    }
    for (; j < end; j++) {
        int s = g_srcs[j];
        float4 v = *reinterpret_cast<const float4*>(g_ys + (size_t)s * HID + part * 4);
        acc.x += v.x; acc.y += v.y; acc.z += v.z; acc.w += v.w;
    }
    *reinterpret_cast<float4*>(g_acc + (size_t)node * HID + part * 4) = acc;
}

// ---------- layer 2 (OUT=1): s1 = ((relu(acc*dinv + b1)) . W2) * dinv ----------
__global__ void k_gemm2(const float* __restrict__ b1,
                        const float* __restrict__ W2, int n) {
    int i = blockIdx.x * blockDim.x + threadIdx.x;
    if (i >= n) return;
    float dinv = g_dinv[i];
    const float4* ar = reinterpret_cast<const float4*>(g_acc + (size_t)i * HID);
    const float4* br = reinterpret_cast<const float4*>(b1);
    const float4* wr = reinterpret_cast<const float4*>(W2);
    float s = 0.0f;
#pragma unroll
    for (int j4 = 0; j4 < HID / 4; j4++) {
        float4 a = ar[j4];
        float4 b = __ldg(&br[j4]);
        float4 w = __ldg(&wr[j4]);
        s += fmaxf(fmaf(a.x, dinv, b.x), 0.0f) * w.x;
        s += fmaxf(fmaf(a.y, dinv, b.y), 0.0f) * w.y;
        s += fmaxf(fmaf(a.z, dinv, b.z), 0.0f) * w.z;
        s += fmaxf(fmaf(a.w, dinv, b.w), 0.0f) * w.w;
    }
    g_s1[i] = s * dinv;
}

// ---------- scalar CSR aggregation ----------
__global__ void k_aggr1(int n) {
    int i = blockIdx.x * blockDim.x + threadIdx.x;
    if (i >= n) return;
    float s = g_s1[i];
    int j   = g_off[i];
    int end = g_off[i + 1];
    for (; j + 4 <= end; j += 4) {
        float v0 = g_s1[g_srcs[j + 0]];
        float v1 = g_s1[g_srcs[j + 1]];
        float v2 = g_s1[g_srcs[j + 2]];
        float v3 = g_s1[g_srcs[j + 3]];
        s += v0 + v1 + v2 + v3;
    }
    for (; j < end; j++) s += g_s1[g_srcs[j]];
    g_s2[i] = s;
}

// ---------- finalize: h2 = s2*dinv + b2 ; out = relu(h2*Wm1+bm1) . Wm2 + bm2 ----------
__global__ void k_final(const float* __restrict__ b2,
                        const float* __restrict__ Wm1,
                        const float* __restrict__ bm1,
                        const float* __restrict__ Wm2,
                        const float* __restrict__ bm2,
                        float* __restrict__ out, int n) {
    int i = blockIdx.x * blockDim.x + threadIdx.x;
    if (i >= n) return;
    float h2 = fmaf(g_s2[i], g_dinv[i], __ldg(b2));
    const float4* w1 = reinterpret_cast<const float4*>(Wm1);
    const float4* bb = reinterpret_cast<const float4*>(bm1);
    const float4* w2 = reinterpret_cast<const float4*>(Wm2);
    float s = __ldg(bm2);
#pragma unroll
    for (int j4 = 0; j4 < HID / 4; j4++) {
        float4 a = __ldg(&w1[j4]);
        float4 b = __ldg(&bb[j4]);
        float4 c = __ldg(&w2[j4]);
        s += fmaxf(fmaf(h2, a.x, b.x), 0.0f) * c.x;
        s += fmaxf(fmaf(h2, a.y, b.y), 0.0f) * c.y;
        s += fmaxf(fmaf(h2, a.z, b.z), 0.0f) * c.z;
        s += fmaxf(fmaf(h2, a.w, b.w), 0.0f) * c.w;
    }
    out[i] = s;
}

extern "C" void kernel_launch(void* const* d_in, const int* in_sizes, int n_in,
                              void* d_out, int out_size) {
    const float* x   = (const float*)d_in[0];
    const void*  ei  = d_in[1];
    const float* W0  = (const float*)d_in[2];
    const float* b0  = (const float*)d_in[3];
    const float* W1  = (const float*)d_in[4];
    const float* b1  = (const float*)d_in[5];
    const float* W2  = (const float*)d_in[6];
    const float* b2  = (const float*)d_in[7];
    const float* Wm1 = (const float*)d_in[8];
    const float* bm1 = (const float*)d_in[9];
    const float* Wm2 = (const float*)d_in[10];
    const float* bm2 = (const float*)d_in[11];
    float* out = (float*)d_out;

    int n = in_sizes[0] / FIN;   // 100000
    int e = in_sizes[1] / 2;     // 1200000

    // CSR build
    k_detect<<<1, 32>>>((const long long*)ei, e);
    k_zero <<<(n + 255) / 256, 256>>>(n);
    k_count<<<(e + 255) / 256, 256>>>(ei, e);
    k_scan <<<1, 1024>>>(n);
    k_fill <<<(e + 255) / 256, 256>>>(ei, e);

    int gemm_grid = (n + 127) / 128;
    int aggr_grid = (n * 16 + 255) / 256;

    // layer 0
    k_gemm<FIN, false><<<gemm_grid, 256>>>(x, W0, nullptr, n);
    k_aggr<<<aggr_grid, 256>>>(n);
    // layer 1 (fused relu(acc*dinv + b0) on smem-load path)
    k_gemm<HID, true><<<gemm_grid, 256>>>(nullptr, W1, b0, n);
    k_aggr<<<aggr_grid, 256>>>(n);
    // layer 2 (scalar output) + scalar aggregation
    k_gemm2<<<(n + 255) / 256, 256>>>(b1, W2, n);
    k_aggr1<<<(n + 255) / 256, 256>>>(n);
    // finalize + MLP head
    k_final<<<(n + 255) / 256, 256>>>(b2, Wm1, bm1, Wm2, bm2, out, n);
}

// round 5
// speedup vs baseline: 2.1026x; 2.1026x over previous
#include <cuda_runtime.h>
#include <cuda_bf16.h>
#include <cstdint>

#define NN  100000
#define EE  1200000
#define FIN 128
#define HID 64
#define SCAN_TILE 256
#define MAX_PARTS ((NN + SCAN_TILE - 1) / SCAN_TILE)   // 391

// Scratch (static __device__ arrays — no allocation allowed)
__device__ __align__(256) float g_ys [(size_t)NN * HID];   // dinv-scaled features (gather source)
__device__ __align__(256) float g_acc[(size_t)NN * HID];   // aggregation result
__device__ __align__(256) float g_dinv[NN];
__device__ __align__(256) int   g_cnt[NN];
__device__ __align__(256) int   g_off[NN + 1];
__device__ __align__(256) int   g_cur[NN];
__device__ __align__(256) int   g_part[MAX_PARTS];
__device__ __align__(256) int   g_partoff[MAX_PARTS];
__device__ __align__(256) int   g_srcs[EE];                // dst-sorted source ids (CSR)
__device__ __align__(256) float g_s1[NN];                  // scalar layer source
__device__ __align__(256) float g_s2[NN];                  // scalar layer result
__device__ int g_is64;

// ---------- edge dtype detection (int64 vs silently-demoted int32) ----------
__global__ void k_detect(const long long* ei, int e) {
    if (blockIdx.x == 0 && threadIdx.x == 0) {
        int ok = 1;
        int m = e < 64 ? e : 64;
        for (int i = 0; i < m; i++) {
            long long v = ei[i];
            if (v < 0 || v >= NN) { ok = 0; break; }
        }
        g_is64 = ok;
    }
}

__device__ __forceinline__ int edge_at(const void* ei, int is64, size_t idx) {
    if (is64) return (int)((const long long*)ei)[idx];
    return ((const int*)ei)[idx];
}

// ---------- CSR build: histogram -> two-level scan -> fill ----------
__global__ void k_zero(int n) {
    int i = blockIdx.x * blockDim.x + threadIdx.x;
    if (i < n) g_cnt[i] = 0;
}

__global__ void k_count(const void* ei, int e) {
    int i = blockIdx.x * blockDim.x + threadIdx.x;
    if (i >= e) return;
    int is64 = g_is64;
    int dst = edge_at(ei, is64, (size_t)e + i);
    atomicAdd(&g_cnt[dst], 1);
}

// level 1: per-block (256-wide) reduction of g_cnt tiles
__global__ __launch_bounds__(SCAN_TILE) void k_blocksum(int n) {
    __shared__ int wsum[SCAN_TILE / 32];
    int t = threadIdx.x;
    int i = blockIdx.x * SCAN_TILE + t;
    int v = (i < n) ? g_cnt[i] : 0;
#pragma unroll
    for (int d = 16; d > 0; d >>= 1) v += __shfl_down_sync(0xffffffffu, v, d);
    if ((t & 31) == 0) wsum[t >> 5] = v;
    __syncthreads();
    if (t < SCAN_TILE / 32) {
        int s = wsum[t];
#pragma unroll
        for (int d = (SCAN_TILE / 64); d > 0; d >>= 1)
            s += __shfl_down_sync(0xffu, s, d);
        if (t == 0) g_part[blockIdx.x] = s;
    }
}

// level 2: single block scans the partials (nb <= 512 here; chunked for safety)
__global__ __launch_bounds__(512) void k_scanpart(int nb, int n) {
    __shared__ int sh[512];
    int t = threadIdx.x;
    int chunk = (nb + 511) >> 9;
    int beg = t * chunk;
    int end = beg + chunk; if (end > nb) end = nb;
    int s = 0;
    for (int i = beg; i < end; i++) s += g_part[i];
    sh[t] = s;
    __syncthreads();
    for (int d = 1; d < 512; d <<= 1) {
        int v = (t >= d) ? sh[t - d] : 0;
        __syncthreads();
        sh[t] += v;
        __syncthreads();
    }
    int off = sh[t] - s;   // exclusive prefix of this thread's chunk
    for (int i = beg; i < end; i++) {
        g_partoff[i] = off;
        off += g_part[i];
    }
    if (t == 511) g_off[n] = sh[511];
}

// level 3: per-block exclusive scan + global offset; emits off/cur/dinv
__global__ __launch_bounds__(SCAN_TILE) void k_finaloff(int n) {
    __shared__ int wexc[SCAN_TILE / 32];
    int t = threadIdx.x;
    int i = blockIdx.x * SCAN_TILE + t;
    int c = (i < n) ? g_cnt[i] : 0;
    int lane = t & 31, warp = t >> 5;
    // inclusive warp scan
    int inc = c;
#pragma unroll
    for (int d = 1; d < 32; d <<= 1) {
        int v = __shfl_up_sync(0xffffffffu, inc, d);
        if (lane >= d) inc += v;
    }
    if (lane == 31) wexc[warp] = inc;
    __syncthreads();
    if (t < SCAN_TILE / 32) {
        int v = wexc[t];
        int e2 = v;
#pragma unroll
        for (int d = 1; d < SCAN_TILE / 32; d <<= 1) {
            int u = __shfl_up_sync(0xffu, e2, d);
            if (t >= d) e2 += u;
        }
        wexc[t] = e2 - v;   // exclusive across warps
    }
    __syncthreads();
    if (i < n) {
        int off = g_partoff[blockIdx.x] + wexc[warp] + (inc - c);
        g_off[i] = off;
        g_cur[i] = off;
        g_dinv[i] = rsqrtf(1.0f + (float)c);
    }
}

__global__ void k_fill(const void* ei, int e) {
    int i = blockIdx.x * blockDim.x + threadIdx.x;
    if (i >= e) return;
    int is64 = g_is64;
    int src = edge_at(ei, is64, (size_t)i);
    int dst = edge_at(ei, is64, (size_t)e + i);
    int pos = atomicAdd(&g_cur[dst], 1);
    g_srcs[pos] = src;
}

// ---------- tiled SGEMM: ys = (A @ W) * dinv ----------
// BM=128, BN=64, BK=16, 256 threads, per-thread 8x4 micro-tile.
// FUSE: A := relu(g_acc * dinv[row] + bias[k]) applied on the smem-load path.
template <int K, bool FUSE>
__global__ __launch_bounds__(256)
void k_gemm(const float* __restrict__ A, const float* __restrict__ W,
            const float* __restrict__ bias, int n) {
    constexpr int BM = 128, BN = 64, BK = 16;
    __shared__ float Ws[K * BN];       // whole W resident
    __shared__ float As[BK][BM];       // k-major A tile (transposed on load)

    int tid = threadIdx.x;
    for (int i = tid; i < (K * BN) / 4; i += 256)
        reinterpret_cast<float4*>(Ws)[i] = reinterpret_cast<const float4*>(W)[i];

    int tx = tid & 15;        // col group: 4 cols
    int ty = tid >> 4;        // row group: 8 rows
    int row0 = blockIdx.x * BM;

    float acc[8][4];
#pragma unroll
    for (int r = 0; r < 8; r++)
#pragma unroll
        for (int c = 0; c < 4; c++) acc[r][c] = 0.0f;

    const float* Asrc = FUSE ? g_acc : A;

    for (int k0 = 0; k0 < K; k0 += BK) {
        __syncthreads();
        // load+transpose A chunk: 512 float4 loads, 2 per thread
#pragma unroll
        for (int l = 0; l < 2; l++) {
            int lin = tid + l * 256;         // 0..511
            int row = lin & 127;
            int kq  = lin >> 7;              // 0..3
            int grow = row0 + row;
            float4 v = make_float4(0.f, 0.f, 0.f, 0.f);
            if (grow < n)
                v = *reinterpret_cast<const float4*>(Asrc + (size_t)grow * K + k0 + kq * 4);
            if (FUSE) {
                float di = (grow < n) ? g_dinv[grow] : 1.0f;
                v.x = fmaxf(fmaf(v.x, di, __ldg(&bias[k0 + kq * 4 + 0])), 0.0f);
                v.y = fmaxf(fmaf(v.y, di, __ldg(&bias[k0 + kq * 4 + 1])), 0.0f);
                v.z = fmaxf(fmaf(v.z, di, __ldg(&bias[k0 + kq * 4 + 2])), 0.0f);
                v.w = fmaxf(fmaf(v.w, di, __ldg(&bias[k0 + kq * 4 + 3])), 0.0f);
            }
            As[kq * 4 + 0][row] = v.x;
            As[kq * 4 + 1][row] = v.y;
            As[kq * 4 + 2][row] = v.z;
            As[kq * 4 + 3][row] = v.w;
        }
        __syncthreads();

#pragma unroll
        for (int k = 0; k < BK; k++) {
            float4 b  = *reinterpret_cast<const float4*>(&Ws[(k0 + k) * BN + tx * 4]);
            float4 a0 = *reinterpret_cast<const float4*>(&As[k][ty * 8]);
            float4 a1 = *reinterpret_cast<const float4*>(&As[k][ty * 8 + 4]);
            float a[8] = {a0.x, a0.y, a0.z, a0.w, a1.x, a1.y, a1.z, a1.w};
            float bb[4] = {b.x, b.y, b.z, b.w};
#pragma unroll
            for (int r = 0; r < 8; r++)
#pragma unroll
                for (int c = 0; c < 4; c++)
                    acc[r][c] = fmaf(a[r], bb[c], acc[r][c]);
        }
    }

    // epilogue: scale by dinv[row], write gather source
#pragma unroll
    for (int r = 0; r < 8; r++) {
        int grow = row0 + ty * 8 + r;
        if (grow < n) {
            float di = g_dinv[grow];
            float4 o = make_float4(acc[r][0] * di, acc[r][1] * di,
                                   acc[r][2] * di, acc[r][3] * di);
            *reinterpret_cast<float4*>(g_ys + (size_t)grow * HID + tx * 4) = o;
        }
    }
}

// ---------- CSR pull aggregation: acc[v] = ys[v] + sum_{u in N(v)} ys[u] ----------
// 16 threads per node, float4 per thread, 4-deep neighbor unroll for MLP.
__global__ void k_aggr(int n) {
    int t = blockIdx.x * blockDim.x + threadIdx.x;
    int node = t >> 4;
    if (node >= n) return;
    int part = t & 15;

    float4 acc = *reinterpret_cast<const float4*>(g_ys + (size_t)node * HID + part * 4);
    int j   = g_off[node];
    int end = g_off[node + 1];

    for (; j + 4 <= end; j += 4) {
        int s0 = g_srcs[j + 0], s1 = g_srcs[j + 1];
        int s2 = g_srcs[j + 2], s3 = g_srcs[j + 3];
        float4 v0 = *reinterpret_cast<const float4*>(g_ys + (size_t)s0 * HID + part * 4);
        float4 v1 = *reinterpret_cast<const float4*>(g_ys + (size_t)s1 * HID + part * 4);
        float4 v2 = *reinterpret_cast<const float4*>(g_ys + (size_t)s2 * HID + part * 4);
        float4 v3 = *reinterpret_cast<const float4*>(g_ys + (size_t)s3 * HID + part * 4);
        acc.x += v0.x + v1.x + v2.x + v3.x;
        acc.y += v0.y + v1.y + v2.y + v3.y;
        acc.z += v0.z + v1.z + v2.z + v3.z;
        acc.w += v0.w + v1.w + v2.w + v3.w;
    }
    for (; j < end; j++) {
        int s = g_srcs[j];
        float4 v = *reinterpret_cast<const float4*>(g_ys + (size_t)s * HID + part * 4);
        acc.x += v.x; acc.y += v.y; acc.z += v.z; acc.w += v.w;
    }
    *reinterpret_cast<float4*>(g_acc + (size_t)node * HID + part * 4) = acc;
}

// ---------- layer 2 (OUT=1): s1 = ((relu(acc*dinv + b1)) . W2) * dinv ----------
__global__ void k_gemm2(const float* __restrict__ b1,
                        const float* __restrict__ W2, int n) {
    int i = blockIdx.x * blockDim.x + threadIdx.x;
    if (i >= n) return;
    float dinv = g_dinv[i];
    const float4* ar = reinterpret_cast<const float4*>(g_acc + (size_t)i * HID);
    const float4* br = reinterpret_cast<const float4*>(b1);
    const float4* wr = reinterpret_cast<const float4*>(W2);
    float s = 0.0f;
#pragma unroll
    for (int j4 = 0; j4 < HID / 4; j4++) {
        float4 a = ar[j4];
        float4 b = __ldg(&br[j4]);
        float4 w = __ldg(&wr[j4]);
        s += fmaxf(fmaf(a.x, dinv, b.x), 0.0f) * w.x;
        s += fmaxf(fmaf(a.y, dinv, b.y), 0.0f) * w.y;
        s += fmaxf(fmaf(a.z, dinv, b.z), 0.0f) * w.z;
        s += fmaxf(fmaf(a.w, dinv, b.w), 0.0f) * w.w;
    }
    g_s1[i] = s * dinv;
}

// ---------- scalar CSR aggregation ----------
__global__ void k_aggr1(int n) {
    int i = blockIdx.x * blockDim.x + threadIdx.x;
    if (i >= n) return;
    float s = g_s1[i];
    int j   = g_off[i];
    int end = g_off[i + 1];
    for (; j + 4 <= end; j += 4) {
        float v0 = g_s1[g_srcs[j + 0]];
        float v1 = g_s1[g_srcs[j + 1]];
        float v2 = g_s1[g_srcs[j + 2]];
        float v3 = g_s1[g_srcs[j + 3]];
        s += v0 + v1 + v2 + v3;
    }
    for (; j < end; j++) s += g_s1[g_srcs[j]];
    g_s2[i] = s;
}

// ---------- finalize: h2 = s2*dinv + b2 ; out = relu(h2*Wm1+bm1) . Wm2 + bm2 ----------
__global__ void k_final(const float* __restrict__ b2,
                        const float* __restrict__ Wm1,
                        const float* __restrict__ bm1,
                        const float* __restrict__ Wm2,
                        const float* __restrict__ bm2,
                        float* __restrict__ out, int n) {
    int i = blockIdx.x * blockDim.x + threadIdx.x;
    if (i >= n) return;
    float h2 = fmaf(g_s2[i], g_dinv[i], __ldg(b2));
    const float4* w1 = reinterpret_cast<const float4*>(Wm1);
    const float4* bb = reinterpret_cast<const float4*>(bm1);
    const float4* w2 = reinterpret_cast<const float4*>(Wm2);
    float s = __ldg(bm2);
#pragma unroll
    for (int j4 = 0; j4 < HID / 4; j4++) {
        float4 a = __ldg(&w1[j4]);
        float4 b = __ldg(&bb[j4]);
        float4 c = __ldg(&w2[j4]);
        s += fmaxf(fmaf(h2, a.x, b.x), 0.0f) * c.x;
        s += fmaxf(fmaf(h2, a.y, b.y), 0.0f) * c.y;
        s += fmaxf(fmaf(h2, a.z, b.z), 0.0f) * c.z;
        s += fmaxf(fmaf(h2, a.w, b.w), 0.0f) * c.w;
    }
    out[i] = s;
}

extern "C" void kernel_launch(void* const* d_in, const int* in_sizes, int n_in,
                              void* d_out, int out_size) {
    const float* x   = (const float*)d_in[0];
    const void*  ei  = d_in[1];
    const float* W0  = (const float*)d_in[2];
    const float* b0  = (const float*)d_in[3];
    const float* W1  = (const float*)d_in[4];
    const float* b1  = (const float*)d_in[5];
    const float* W2  = (const float*)d_in[6];
    const float* b2  = (const float*)d_in[7];
    const float* Wm1 = (const float*)d_in[8];
    const float* bm1 = (const float*)d_in[9];
    const float* Wm2 = (const float*)d_in[10];
    const float* bm2 = (const float*)d_in[11];
    float* out = (float*)d_out;

    int n = in_sizes[0] / FIN;   // 100000
    int e = in_sizes[1] / 2;     // 1200000

    int nb = (n + SCAN_TILE - 1) / SCAN_TILE;   // 391

    // CSR build (two-level scan)
    k_detect<<<1, 32>>>((const long long*)ei, e);
    k_zero <<<(n + 255) / 256, 256>>>(n);
    k_count<<<(e + 255) / 256, 256>>>(ei, e);
    k_blocksum<<<nb, SCAN_TILE>>>(n);
    k_scanpart<<<1, 512>>>(nb, n);
    k_finaloff<<<nb, SCAN_TILE>>>(n);
    k_fill <<<(e + 255) / 256, 256>>>(ei, e);

    int gemm_grid = (n + 127) / 128;
    int aggr_grid = (n * 16 + 255) / 256;

    // layer 0
    k_gemm<FIN, false><<<gemm_grid, 256>>>(x, W0, nullptr, n);
    k_aggr<<<aggr_grid, 256>>>(n);
    // layer 1 (fused relu(acc*dinv + b0) on smem-load path)
    k_gemm<HID, true><<<gemm_grid, 256>>>(nullptr, W1, b0, n);
    k_aggr<<<aggr_grid, 256>>>(n);
    // layer 2 (scalar output) + scalar aggregation
    k_gemm2<<<(n + 255) / 256, 256>>>(b1, W2, n);
    k_aggr1<<<(n + 255) / 256, 256>>>(n);
    // finalize + MLP head
    k_final<<<(n + 255) / 256, 256>>>(b2, Wm1, bm1, Wm2, bm2, out, n);
}

// round 7
// speedup vs baseline: 2.1831x; 1.0383x over previous
#include <cuda_runtime.h>
#include <cuda_bf16.h>
#include <cstdint>

#define NN  100000
#define EE  1200000
#define FIN 128
#define HID 64
#define SCAN_TILE 256
#define MAX_PARTS ((NN + SCAN_TILE - 1) / SCAN_TILE)   // 391

// Scratch (static __device__ arrays — no allocation allowed)
__device__ __align__(256) float g_ys [(size_t)NN * HID];   // RAW gemm output (gather source)
__device__ __align__(256) float g_acc[(size_t)NN * HID];   // normalized aggregation result
__device__ __align__(256) float g_dinv[NN];
__device__ __align__(256) int   g_cnt[NN];
__device__ __align__(256) int   g_off[NN + 1];
__device__ __align__(256) int   g_cur[NN];
__device__ __align__(256) int   g_part[MAX_PARTS];
__device__ __align__(256) int   g_partoff[MAX_PARTS];
__device__ __align__(256) int   g_srcs[EE];                // dst-sorted source ids (CSR)
__device__ __align__(256) float g_s1[NN];                  // scalar layer source (pre-scaled by dinv)
__device__ __align__(256) float g_s2[NN];                  // scalar layer result
__device__ int g_is64;

// ---------- f32x2 packed-FMA helpers ----------
__device__ __forceinline__ unsigned long long ffma2(unsigned long long a,
                                                    unsigned long long b,
                                                    unsigned long long c) {
    unsigned long long d;
    asm("fma.rn.f32x2 %0, %1, %2, %3;" : "=l"(d) : "l"(a), "l"(b), "l"(c));
    return d;
}
__device__ __forceinline__ unsigned long long dup2(float x) {
    unsigned long long d;
    unsigned int u = __float_as_uint(x);
    asm("mov.b64 %0, {%1, %1};" : "=l"(d) : "r"(u));
    return d;
}

// ---------- edge dtype detection (int64 vs silently-demoted int32), parallel ----------
__global__ void k_detect(const long long* ei, int e) {
    int t = threadIdx.x;
    int m = e < 32 ? e : 32;
    int bad = 0;
    if (t < m) {
        long long v = ei[t];
        if (v < 0 || v >= NN) bad = 1;
    }
    unsigned int anybad = __ballot_sync(0xffffffffu, bad);
    if (t == 0) g_is64 = (anybad == 0u);
}

__device__ __forceinline__ int edge_at(const void* ei, int is64, size_t idx) {
    if (is64) return (int)((const long long*)ei)[idx];
    return ((const int*)ei)[idx];
}

// ---------- CSR build: histogram -> two-level scan -> fill ----------
__global__ void k_zero(int n) {
    int i = blockIdx.x * blockDim.x + threadIdx.x;
    if (i < n) g_cnt[i] = 0;
}

__global__ void k_count(const void* ei, int e) {
    int i = blockIdx.x * blockDim.x + threadIdx.x;
    if (i >= e) return;
    int is64 = g_is64;
    int dst = edge_at(ei, is64, (size_t)e + i);
    atomicAdd(&g_cnt[dst], 1);
}

__global__ __launch_bounds__(SCAN_TILE) void k_blocksum(int n) {
    __shared__ int wsum[SCAN_TILE / 32];
    int t = threadIdx.x;
    int i = blockIdx.x * SCAN_TILE + t;
    int v = (i < n) ? g_cnt[i] : 0;
#pragma unroll
    for (int d = 16; d > 0; d >>= 1) v += __shfl_down_sync(0xffffffffu, v, d);
    if ((t & 31) == 0) wsum[t >> 5] = v;
    __syncthreads();
    if (t < SCAN_TILE / 32) {
        int s = wsum[t];
#pragma unroll
        for (int d = (SCAN_TILE / 64); d > 0; d >>= 1)
            s += __shfl_down_sync(0xffu, s, d);
        if (t == 0) g_part[blockIdx.x] = s;
    }
}

__global__ __launch_bounds__(512) void k_scanpart(int nb, int n) {
    __shared__ int sh[512];
    int t = threadIdx.x;
    int chunk = (nb + 511) >> 9;
    int beg = t * chunk;
    int end = beg + chunk; if (end > nb) end = nb;
    int s = 0;
    for (int i = beg; i < end; i++) s += g_part[i];
    sh[t] = s;
    __syncthreads();
    for (int d = 1; d < 512; d <<= 1) {
        int v = (t >= d) ? sh[t - d] : 0;
        __syncthreads();
        sh[t] += v;
        __syncthreads();
    }
    int off = sh[t] - s;
    for (int i = beg; i < end; i++) {
        g_partoff[i] = off;
        off += g_part[i];
    }
    if (t == 511) g_off[n] = sh[511];
}

__global__ __launch_bounds__(SCAN_TILE) void k_finaloff(int n) {
    __shared__ int wexc[SCAN_TILE / 32];
    int t = threadIdx.x;
    int i = blockIdx.x * SCAN_TILE + t;
    int c = (i < n) ? g_cnt[i] : 0;
    int lane = t & 31, warp = t >> 5;
    int inc = c;
#pragma unroll
    for (int d = 1; d < 32; d <<= 1) {
        int v = __shfl_up_sync(0xffffffffu, inc, d);
        if (lane >= d) inc += v;
    }
    if (lane == 31) wexc[warp] = inc;
    __syncthreads();
    if (t < SCAN_TILE / 32) {
        int v = wexc[t];
        int e2 = v;
#pragma unroll
        for (int d = 1; d < SCAN_TILE / 32; d <<= 1) {
            int u = __shfl_up_sync(0xffu, e2, d);
            if (t >= d) e2 += u;
        }
        wexc[t] = e2 - v;
    }
    __syncthreads();
    if (i < n) {
        int off = g_partoff[blockIdx.x] + wexc[warp] + (inc - c);
        g_off[i] = off;
        g_cur[i] = off;
        g_dinv[i] = rsqrtf(1.0f + (float)c);
    }
}

__global__ void k_fill(const void* ei, int e) {
    int i = blockIdx.x * blockDim.x + threadIdx.x;
    if (i >= e) return;
    int is64 = g_is64;
    int src = edge_at(ei, is64, (size_t)i);
    int dst = edge_at(ei, is64, (size_t)e + i);
    int pos = atomicAdd(&g_cur[dst], 1);
    g_srcs[pos] = src;
}

// ---------- tiled SGEMM (f32x2 packed): ys = A @ W  (RAW, no dinv) ----------
// BM=128, BN=64, BK=16, 256 threads; per-thread 8 rows x 4 cols, rows paired for FFMA2.
// FUSE: A := relu(g_acc + bias[k]) applied on the smem-load path (g_acc already normalized).
template <int K, bool FUSE>
__global__ __launch_bounds__(256)
void k_gemm(const float* __restrict__ A, const float* __restrict__ W,
            const float* __restrict__ bias, int n) {
    constexpr int BM = 128, BN = 64, BK = 16;
    __shared__ float Ws[K * BN];       // whole W resident
    __shared__ float As[BK][BM];       // k-major A tile (transposed on load)

    int tid = threadIdx.x;
    for (int i = tid; i < (K * BN) / 4; i += 256)
        reinterpret_cast<float4*>(Ws)[i] = reinterpret_cast<const float4*>(W)[i];

    int tx = tid & 15;        // 4 cols
    int ty = tid >> 4;        // 8 rows (4 row-pairs)
    int row0 = blockIdx.x * BM;

    unsigned long long acc2[4][4];     // [row-pair][col], lo=even row, hi=odd row
#pragma unroll
    for (int r = 0; r < 4; r++)
#pragma unroll
        for (int c = 0; c < 4; c++) acc2[r][c] = 0ULL;

    const float* Asrc = FUSE ? g_acc : A;

    for (int k0 = 0; k0 < K; k0 += BK) {
        __syncthreads();
#pragma unroll
        for (int l = 0; l < 2; l++) {
            int lin = tid + l * 256;         // 0..511
            int row = lin & 127;
            int kq  = lin >> 7;              // 0..3
            int grow = row0 + row;
            float4 v = make_float4(0.f, 0.f, 0.f, 0.f);
            if (grow < n)
                v = *reinterpret_cast<const float4*>(Asrc + (size_t)grow * K + k0 + kq * 4);
            if (FUSE) {
                v.x = fmaxf(v.x + __ldg(&bias[k0 + kq * 4 + 0]), 0.0f);
                v.y = fmaxf(v.y + __ldg(&bias[k0 + kq * 4 + 1]), 0.0f);
                v.z = fmaxf(v.z + __ldg(&bias[k0 + kq * 4 + 2]), 0.0f);
                v.w = fmaxf(v.w + __ldg(&bias[k0 + kq * 4 + 3]), 0.0f);
            }
            As[kq * 4 + 0][row] = v.x;
            As[kq * 4 + 1][row] = v.y;
            As[kq * 4 + 2][row] = v.z;
            As[kq * 4 + 3][row] = v.w;
        }
        __syncthreads();

#pragma unroll
        for (int k = 0; k < BK; k++) {
            float4 b = *reinterpret_cast<const float4*>(&Ws[(k0 + k) * BN + tx * 4]);
            unsigned long long bp[4] = {dup2(b.x), dup2(b.y), dup2(b.z), dup2(b.w)};
            const ulonglong2* ar =
                reinterpret_cast<const ulonglong2*>(&As[k][ty * 8]);
            ulonglong2 a01 = ar[0];   // row-pairs 0,1
            ulonglong2 a23 = ar[1];   // row-pairs 2,3
            unsigned long long ap[4] = {a01.x, a01.y, a23.x, a23.y};
#pragma unroll
            for (int r = 0; r < 4; r++)
#pragma unroll
                for (int c = 0; c < 4; c++)
                    acc2[r][c] = ffma2(ap[r], bp[c], acc2[r][c]);
        }
    }

    // epilogue: write RAW gemm output
#pragma unroll
    for (int r = 0; r < 4; r++) {
        int ge = row0 + ty * 8 + 2 * r;      // even row
        float2 c0 = *reinterpret_cast<float2*>(&acc2[r][0]);
        float2 c1 = *reinterpret_cast<float2*>(&acc2[r][1]);
        float2 c2 = *reinterpret_cast<float2*>(&acc2[r][2]);
        float2 c3 = *reinterpret_cast<float2*>(&acc2[r][3]);
        if (ge < n) {
            float4 o = make_float4(c0.x, c1.x, c2.x, c3.x);
            *reinterpret_cast<float4*>(g_ys + (size_t)ge * HID + tx * 4) = o;
        }
        if (ge + 1 < n) {
            float4 o = make_float4(c0.y, c1.y, c2.y, c3.y);
            *reinterpret_cast<float4*>(g_ys + (size_t)(ge + 1) * HID + tx * 4) = o;
        }
    }
}

// ---------- CSR pull aggregation (normalized): ----------
// acc[v] = dinv_v * ( dinv_v*ys[v] + sum_u dinv_u*ys[u] )
__global__ void k_aggr(int n) {
    int t = blockIdx.x * blockDim.x + threadIdx.x;
    int node = t >> 4;
    if (node >= n) return;
    int part = t & 15;

    float dv = g_dinv[node];
    float4 self = *reinterpret_cast<const float4*>(g_ys + (size_t)node * HID + part * 4);
    float4 acc;
    acc.x = self.x * dv; acc.y = self.y * dv;
    acc.z = self.z * dv; acc.w = self.w * dv;

    int j   = g_off[node];
    int end = g_off[node + 1];

    for (; j + 4 <= end; j += 4) {
        int s0 = g_srcs[j + 0], s1 = g_srcs[j + 1];
        int s2 = g_srcs[j + 2], s3 = g_srcs[j + 3];
        float d0 = g_dinv[s0], d1 = g_dinv[s1], d2 = g_dinv[s2], d3 = g_dinv[s3];
        float4 v0 = *reinterpret_cast<const float4*>(g_ys + (size_t)s0 * HID + part * 4);
        float4 v1 = *reinterpret_cast<const float4*>(g_ys + (size_t)s1 * HID + part * 4);
        float4 v2 = *reinterpret_cast<const float4*>(g_ys + (size_t)s2 * HID + part * 4);
        float4 v3 = *reinterpret_cast<const float4*>(g_ys + (size_t)s3 * HID + part * 4);
        acc.x = fmaf(d0, v0.x, fmaf(d1, v1.x, fmaf(d2, v2.x, fmaf(d3, v3.x, acc.x))));
        acc.y = fmaf(d0, v0.y, fmaf(d1, v1.y, fmaf(d2, v2.y, fmaf(d3, v3.y, acc.y))));
        acc.z = fmaf(d0, v0.z, fmaf(d1, v1.z, fmaf(d2, v2.z, fmaf(d3, v3.z, acc.z))));
        acc.w = fmaf(d0, v0.w, fmaf(d1, v1.w, fmaf(d2, v2.w, fmaf(d3, v3.w, acc.w))));
    }
    for (; j < end; j++) {
        int s = g_srcs[j];
        float du = g_dinv[s];
        float4 v = *reinterpret_cast<const float4*>(g_ys + (size_t)s * HID + part * 4);
        acc.x = fmaf(du, v.x, acc.x); acc.y = fmaf(du, v.y, acc.y);
        acc.z = fmaf(du, v.z, acc.z); acc.w = fmaf(du, v.w, acc.w);
    }
    acc.x *= dv; acc.y *= dv; acc.z *= dv; acc.w *= dv;
    *reinterpret_cast<float4*>(g_acc + (size_t)node * HID + part * 4) = acc;
}

// ---------- layer 2 (OUT=1): s1[i] = dinv_i * ( relu(acc + b1) . W2 ) ----------
__global__ void k_gemm2(const float* __restrict__ b1,
                        const float* __restrict__ W2, int n) {
    int i = blockIdx.x * blockDim.x + threadIdx.x;
    if (i >= n) return;
    const float4* ar = reinterpret_cast<const float4*>(g_acc + (size_t)i * HID);
    const float4* br = reinterpret_cast<const float4*>(b1);
    const float4* wr = reinterpret_cast<const float4*>(W2);
    float s = 0.0f;
#pragma unroll
    for (int j4 = 0; j4 < HID / 4; j4++) {
        float4 a = ar[j4];
        float4 b = __ldg(&br[j4]);
        float4 w = __ldg(&wr[j4]);
        s += fmaxf(a.x + b.x, 0.0f) * w.x;
        s += fmaxf(a.y + b.y, 0.0f) * w.y;
        s += fmaxf(a.z + b.z, 0.0f) * w.z;
        s += fmaxf(a.w + b.w, 0.0f) * w.w;
    }
    g_s1[i] = s * g_dinv[i];
}

// ---------- scalar CSR aggregation: s2[v] = dinv_v * ( s1[v] + sum_u s1[u] ) ----------
__global__ void k_aggr1(int n) {
    int i = blockIdx.x * blockDim.x + threadIdx.x;
    if (i >= n) return;
    float s = g_s1[i];
    int j   = g_off[i];
    int end = g_off[i + 1];
    for (; j + 4 <= end; j += 4) {
        float v0 = g_s1[g_srcs[j + 0]];
        float v1 = g_s1[g_srcs[j + 1]];
        float v2 = g_s1[g_srcs[j + 2]];
        float v3 = g_s1[g_srcs[j + 3]];
        s += v0 + v1 + v2 + v3;
    }
    for (; j < end; j++) s += g_s1[g_srcs[j]];
    g_s2[i] = s * g_dinv[i];
}

// ---------- finalize: h2 = s2 + b2 ; out = relu(h2*Wm1+bm1) . Wm2 + bm2 ----------
__global__ void k_final(const float* __restrict__ b2,
                        const float* __restrict__ Wm1,
                        const float* __restrict__ bm1,
                        const float* __restrict__ Wm2,
                        const float* __restrict__ bm2,
                        float* __restrict__ out, int n) {
    int i = blockIdx.x * blockDim.x + threadIdx.x;
    if (i >= n) return;
    float h2 = g_s2[i] + __ldg(b2);
    const float4* w1 = reinterpret_cast<const float4*>(Wm1);
    const float4* bb = reinterpret_cast<const float4*>(bm1);
    const float4* w2 = reinterpret_cast<const float4*>(Wm2);
    float s = __ldg(bm2);
#pragma unroll
    for (int j4 = 0; j4 < HID / 4; j4++) {
        float4 a = __ldg(&w1[j4]);
        float4 b = __ldg(&bb[j4]);
        float4 c = __ldg(&w2[j4]);
        s += fmaxf(fmaf(h2, a.x, b.x), 0.0f) * c.x;
        s += fmaxf(fmaf(h2, a.y, b.y), 0.0f) * c.y;
        s += fmaxf(fmaf(h2, a.z, b.z), 0.0f) * c.z;
        s += fmaxf(fmaf(h2, a.w, b.w), 0.0f) * c.w;
    }
    out[i] = s;
}

extern "C" void kernel_launch(void* const* d_in, const int* in_sizes, int n_in,
                              void* d_out, int out_size) {
    const float* x   = (const float*)d_in[0];
    const void*  ei  = d_in[1];
    const float* W0  = (const float*)d_in[2];
    const float* b0  = (const float*)d_in[3];
    const float* W1  = (const float*)d_in[4];
    const float* b1  = (const float*)d_in[5];
    const float* W2  = (const float*)d_in[6];
    const float* b2  = (const float*)d_in[7];
    const float* Wm1 = (const float*)d_in[8];
    const float* bm1 = (const float*)d_in[9];
    const float* Wm2 = (const float*)d_in[10];
    const float* bm2 = (const float*)d_in[11];
    float* out = (float*)d_out;

    int n = in_sizes[0] / FIN;   // 100000
    int e = in_sizes[1] / 2;     // 1200000
    int nb = (n + SCAN_TILE - 1) / SCAN_TILE;   // 391

    // one-time host objects for the fork/join (host-side only; no device mem)
    static cudaStream_t sB = nullptr;
    static cudaEvent_t evFork = nullptr, evJoin = nullptr;
    if (sB == nullptr) {
        cudaStreamCreateWithFlags(&sB, cudaStreamNonBlocking);
        cudaEventCreateWithFlags(&evFork, cudaEventDisableTiming);
        cudaEventCreateWithFlags(&evJoin, cudaEventDisableTiming);
    }

    int gemm_grid = (n + 127) / 128;
    int aggr_grid = (n * 16 + 255) / 256;

    // ---- fork: GEMM0 (independent of graph structure) on sB ----
    cudaEventRecord(evFork, 0);
    cudaStreamWaitEvent(sB, evFork, 0);
    k_gemm<FIN, false><<<gemm_grid, 256, 0, sB>>>(x, W0, nullptr, n);
    cudaEventRecord(evJoin, sB);

    // ---- CSR build on default stream (runs concurrently with GEMM0) ----
    k_detect<<<1, 32>>>((const long long*)ei, e);
    k_zero <<<(n + 255) / 256, 256>>>(n);
    k_count<<<(e + 255) / 256, 256>>>(ei, e);
    k_blocksum<<<nb, SCAN_TILE>>>(n);
    k_scanpart<<<1, 512>>>(nb, n);
    k_finaloff<<<nb, SCAN_TILE>>>(n);
    k_fill <<<(e + 255) / 256, 256>>>(ei, e);

    // ---- join ----
    cudaStreamWaitEvent(0, evJoin, 0);

    // layer 0 aggregation
    k_aggr<<<aggr_grid, 256>>>(n);
    // layer 1 (fused relu(acc + b0) on smem-load path)
    k_gemm<HID, true><<<gemm_grid, 256>>>(nullptr, W1, b0, n);
    k_aggr<<<aggr_grid, 256>>>(n);
    // layer 2 (scalar output) + scalar aggregation
    k_gemm2<<<(n + 255) / 256, 256>>>(b1, W2, n);
    k_aggr1<<<(n + 255) / 256, 256>>>(n);
    // finalize + MLP head
    k_final<<<(n + 255) / 256, 256>>>(b2, Wm1, bm1, Wm2, bm2, out, n);
}

// round 9
// speedup vs baseline: 2.3924x; 1.0959x over previous
#include <cuda_runtime.h>
#include <cuda_bf16.h>
#include <cstdint>

#define NN  100000
#define EE  1200000
#define FIN 128
#define HID 64
#define SCAN_TILE 256
#define MAX_PARTS ((NN + SCAN_TILE - 1) / SCAN_TILE)   // 391

// Scratch (static __device__ arrays — no allocation allowed)
__device__ __align__(256) float g_ys [(size_t)NN * HID];   // layer-0 gemm output (gather source)
__device__ __align__(256) float g_ys2[(size_t)NN * HID];   // layer-1 gemm output (gather source)
__device__ __align__(256) float g_dinv[NN];
__device__ __align__(256) int   g_cnt[NN];
__device__ __align__(256) int   g_off[NN + 1];
__device__ __align__(256) int   g_cur[NN];
__device__ __align__(256) int   g_part[MAX_PARTS];
__device__ __align__(256) int   g_partoff[MAX_PARTS];
__device__ __align__(256) int   g_srcs[EE];                // dst-sorted source ids (CSR)
__device__ __align__(256) float g_s1[NN];                  // scalar layer source (pre-scaled by dinv)
__device__ int g_is64;

// ---------- f32x2 packed-FMA helpers ----------
__device__ __forceinline__ unsigned long long ffma2(unsigned long long a,
                                                    unsigned long long b,
                                                    unsigned long long c) {
    unsigned long long d;
    asm("fma.rn.f32x2 %0, %1, %2, %3;" : "=l"(d) : "l"(a), "l"(b), "l"(c));
    return d;
}
__device__ __forceinline__ unsigned long long dup2(float x) {
    unsigned long long d;
    unsigned int u = __float_as_uint(x);
    asm("mov.b64 %0, {%1, %1};" : "=l"(d) : "r"(u));
    return d;
}

__device__ __forceinline__ int edge_at(const void* ei, int is64, size_t idx) {
    if (is64) return (int)((const long long*)ei)[idx];
    return ((const int*)ei)[idx];
}

// ---------- zero + edge-dtype detection (merged) ----------
__global__ void k_zero_detect(const long long* ei, int e, int n) {
    int i = blockIdx.x * blockDim.x + threadIdx.x;
    if (i < n) g_cnt[i] = 0;
    if (blockIdx.x == 0 && threadIdx.x < 32) {
        int t = threadIdx.x;
        int m = e < 32 ? e : 32;
        int bad = 0;
        if (t < m) {
            long long v = ei[t];
            if (v < 0 || v >= NN) bad = 1;
        }
        unsigned int anybad = __ballot_sync(0xffffffffu, bad);
        if (t == 0) g_is64 = (anybad == 0u);
    }
}

// ---------- CSR build: histogram -> two-level scan -> fill ----------
__global__ void k_count(const void* ei, int e) {
    int i = blockIdx.x * blockDim.x + threadIdx.x;
    if (i >= e) return;
    int is64 = g_is64;
    int dst = edge_at(ei, is64, (size_t)e + i);
    atomicAdd(&g_cnt[dst], 1);
}

__global__ __launch_bounds__(SCAN_TILE) void k_blocksum(int n) {
    __shared__ int wsum[SCAN_TILE / 32];
    int t = threadIdx.x;
    int i = blockIdx.x * SCAN_TILE + t;
    int v = (i < n) ? g_cnt[i] : 0;
#pragma unroll
    for (int d = 16; d > 0; d >>= 1) v += __shfl_down_sync(0xffffffffu, v, d);
    if ((t & 31) == 0) wsum[t >> 5] = v;
    __syncthreads();
    if (t < SCAN_TILE / 32) {
        int s = wsum[t];
#pragma unroll
        for (int d = (SCAN_TILE / 64); d > 0; d >>= 1)
            s += __shfl_down_sync(0xffu, s, d);
        if (t == 0) g_part[blockIdx.x] = s;
    }
}

__global__ __launch_bounds__(512) void k_scanpart(int nb, int n) {
    __shared__ int sh[512];
    int t = threadIdx.x;
    int chunk = (nb + 511) >> 9;
    int beg = t * chunk;
    int end = beg + chunk; if (end > nb) end = nb;
    int s = 0;
    for (int i = beg; i < end; i++) s += g_part[i];
    sh[t] = s;
    __syncthreads();
    for (int d = 1; d < 512; d <<= 1) {
        int v = (t >= d) ? sh[t - d] : 0;
        __syncthreads();
        sh[t] += v;
        __syncthreads();
    }
    int off = sh[t] - s;
    for (int i = beg; i < end; i++) {
        g_partoff[i] = off;
        off += g_part[i];
    }
    if (t == 511) g_off[n] = sh[511];
}

__global__ __launch_bounds__(SCAN_TILE) void k_finaloff(int n) {
    __shared__ int wexc[SCAN_TILE / 32];
    int t = threadIdx.x;
    int i = blockIdx.x * SCAN_TILE + t;
    int c = (i < n) ? g_cnt[i] : 0;
    int lane = t & 31, warp = t >> 5;
    int inc = c;
#pragma unroll
    for (int d = 1; d < 32; d <<= 1) {
        int v = __shfl_up_sync(0xffffffffu, inc, d);
        if (lane >= d) inc += v;
    }
    if (lane == 31) wexc[warp] = inc;
    __syncthreads();
    if (t < SCAN_TILE / 32) {
        int v = wexc[t];
        int e2 = v;
#pragma unroll
        for (int d = 1; d < SCAN_TILE / 32; d <<= 1) {
            int u = __shfl_up_sync(0xffu, e2, d);
            if (t >= d) e2 += u;
        }
        wexc[t] = e2 - v;
    }
    __syncthreads();
    if (i < n) {
        int off = g_partoff[blockIdx.x] + wexc[warp] + (inc - c);
        g_off[i] = off;
        g_cur[i] = off;
        g_dinv[i] = rsqrtf(1.0f + (float)c);
    }
}

__global__ void k_fill(const void* ei, int e) {
    int i = blockIdx.x * blockDim.x + threadIdx.x;
    if (i >= e) return;
    int is64 = g_is64;
    int src = edge_at(ei, is64, (size_t)i);
    int dst = edge_at(ei, is64, (size_t)e + i);
    int pos = atomicAdd(&g_cur[dst], 1);
    g_srcs[pos] = src;
}

// ---------- normalized pull of one node-part: acc = dv*(dv*self + sum du*nb) ----------
__device__ __forceinline__ float4 aggr_part(const float* __restrict__ src,
                                            int node, int part) {
    float dv = g_dinv[node];
    float4 self = *reinterpret_cast<const float4*>(src + (size_t)node * HID + part * 4);
    float4 acc;
    acc.x = self.x * dv; acc.y = self.y * dv;
    acc.z = self.z * dv; acc.w = self.w * dv;

    int j   = g_off[node];
    int end = g_off[node + 1];
    for (; j + 4 <= end; j += 4) {
        int s0 = g_srcs[j + 0], s1 = g_srcs[j + 1];
        int s2 = g_srcs[j + 2], s3 = g_srcs[j + 3];
        float d0 = g_dinv[s0], d1 = g_dinv[s1], d2 = g_dinv[s2], d3 = g_dinv[s3];
        float4 v0 = *reinterpret_cast<const float4*>(src + (size_t)s0 * HID + part * 4);
        float4 v1 = *reinterpret_cast<const float4*>(src + (size_t)s1 * HID + part * 4);
        float4 v2 = *reinterpret_cast<const float4*>(src + (size_t)s2 * HID + part * 4);
        float4 v3 = *reinterpret_cast<const float4*>(src + (size_t)s3 * HID + part * 4);
        acc.x = fmaf(d0, v0.x, fmaf(d1, v1.x, fmaf(d2, v2.x, fmaf(d3, v3.x, acc.x))));
        acc.y = fmaf(d0, v0.y, fmaf(d1, v1.y, fmaf(d2, v2.y, fmaf(d3, v3.y, acc.y))));
        acc.z = fmaf(d0, v0.z, fmaf(d1, v1.z, fmaf(d2, v2.z, fmaf(d3, v3.z, acc.z))));
        acc.w = fmaf(d0, v0.w, fmaf(d1, v1.w, fmaf(d2, v2.w, fmaf(d3, v3.w, acc.w))));
    }
    for (; j < end; j++) {
        int s = g_srcs[j];
        float du = g_dinv[s];
        float4 v = *reinterpret_cast<const float4*>(src + (size_t)s * HID + part * 4);
        acc.x = fmaf(du, v.x, acc.x); acc.y = fmaf(du, v.y, acc.y);
        acc.z = fmaf(du, v.z, acc.z); acc.w = fmaf(du, v.w, acc.w);
    }
    acc.x *= dv; acc.y *= dv; acc.z *= dv; acc.w *= dv;
    return acc;
}

// ---------- tiled SGEMM (f32x2 packed): ys = A @ W  (layer 0, K=128) ----------
template <int K>
__global__ __launch_bounds__(256)
void k_gemm(const float* __restrict__ A, const float* __restrict__ W, int n) {
    constexpr int BM = 128, BN = 64, BK = 16;
    __shared__ float Ws[K * BN];
    __shared__ float As[BK][BM];

    int tid = threadIdx.x;
    for (int i = tid; i < (K * BN) / 4; i += 256)
        reinterpret_cast<float4*>(Ws)[i] = reinterpret_cast<const float4*>(W)[i];

    int tx = tid & 15;
    int ty = tid >> 4;
    int row0 = blockIdx.x * BM;

    unsigned long long acc2[4][4];
#pragma unroll
    for (int r = 0; r < 4; r++)
#pragma unroll
        for (int c = 0; c < 4; c++) acc2[r][c] = 0ULL;

    for (int k0 = 0; k0 < K; k0 += BK) {
        __syncthreads();
#pragma unroll
        for (int l = 0; l < 2; l++) {
            int lin = tid + l * 256;
            int row = lin & 127;
            int kq  = lin >> 7;
            int grow = row0 + row;
            float4 v = make_float4(0.f, 0.f, 0.f, 0.f);
            if (grow < n)
                v = *reinterpret_cast<const float4*>(A + (size_t)grow * K + k0 + kq * 4);
            As[kq * 4 + 0][row] = v.x;
            As[kq * 4 + 1][row] = v.y;
            As[kq * 4 + 2][row] = v.z;
            As[kq * 4 + 3][row] = v.w;
        }
        __syncthreads();

#pragma unroll
        for (int k = 0; k < BK; k++) {
            float4 b = *reinterpret_cast<const float4*>(&Ws[(k0 + k) * BN + tx * 4]);
            unsigned long long bp[4] = {dup2(b.x), dup2(b.y), dup2(b.z), dup2(b.w)};
            const ulonglong2* ar = reinterpret_cast<const ulonglong2*>(&As[k][ty * 8]);
            ulonglong2 a01 = ar[0];
            ulonglong2 a23 = ar[1];
            unsigned long long ap[4] = {a01.x, a01.y, a23.x, a23.y};
#pragma unroll
            for (int r = 0; r < 4; r++)
#pragma unroll
                for (int c = 0; c < 4; c++)
                    acc2[r][c] = ffma2(ap[r], bp[c], acc2[r][c]);
        }
    }

#pragma unroll
    for (int r = 0; r < 4; r++) {
        int ge = row0 + ty * 8 + 2 * r;
        float2 c0 = *reinterpret_cast<float2*>(&acc2[r][0]);
        float2 c1 = *reinterpret_cast<float2*>(&acc2[r][1]);
        float2 c2 = *reinterpret_cast<float2*>(&acc2[r][2]);
        float2 c3 = *reinterpret_cast<float2*>(&acc2[r][3]);
        if (ge < n) {
            float4 o = make_float4(c0.x, c1.x, c2.x, c3.x);
            *reinterpret_cast<float4*>(g_ys + (size_t)ge * HID + tx * 4) = o;
        }
        if (ge + 1 < n) {
            float4 o = make_float4(c0.y, c1.y, c2.y, c3.y);
            *reinterpret_cast<float4*>(g_ys + (size_t)(ge + 1) * HID + tx * 4) = o;
        }
    }
}

// ---------- FUSED: aggr(ys) -> relu(+b0) -> @W1 -> ys2   (K=HID=64) ----------
__global__ __launch_bounds__(256)
void k_fused_ag(const float* __restrict__ W, const float* __restrict__ bias, int n) {
    constexpr int BM = 128, BN = 64, K = 64, AST = 132;
    __shared__ float Ws[K * BN];          // 16 KB
    __shared__ float As[K][AST];          // 33.8 KB, k-major transposed A tile

    int tid = threadIdx.x;
    for (int i = tid; i < (K * BN) / 4; i += 256)
        reinterpret_cast<float4*>(Ws)[i] = reinterpret_cast<const float4*>(W)[i];

    int row0 = blockIdx.x * BM;
    int part = tid & 15;      // feature part: 4 floats
    int grp  = tid >> 4;      // node group within pass

    float4 bk = *reinterpret_cast<const float4*>(bias + part * 4);

    // aggregation phase: 8 passes x 16 nodes
#pragma unroll 1
    for (int p = 0; p < 8; p++) {
        int nl = p * 16 + grp;
        int node = row0 + nl;
        float4 a = make_float4(0.f, 0.f, 0.f, 0.f);
        if (node < n) {
            a = aggr_part(g_ys, node, part);
            a.x = fmaxf(a.x + bk.x, 0.0f);
            a.y = fmaxf(a.y + bk.y, 0.0f);
            a.z = fmaxf(a.z + bk.z, 0.0f);
            a.w = fmaxf(a.w + bk.w, 0.0f);
        }
        As[part * 4 + 0][nl] = a.x;
        As[part * 4 + 1][nl] = a.y;
        As[part * 4 + 2][nl] = a.z;
        As[part * 4 + 3][nl] = a.w;
    }
    __syncthreads();

    // GEMM phase
    int tx = tid & 15;
    int ty = tid >> 4;
    unsigned long long acc2[4][4];
#pragma unroll
    for (int r = 0; r < 4; r++)
#pragma unroll
        for (int c = 0; c < 4; c++) acc2[r][c] = 0ULL;

#pragma unroll 8
    for (int k = 0; k < K; k++) {
        float4 b = *reinterpret_cast<const float4*>(&Ws[k * BN + tx * 4]);
        unsigned long long bp[4] = {dup2(b.x), dup2(b.y), dup2(b.z), dup2(b.w)};
        const ulonglong2* ar = reinterpret_cast<const ulonglong2*>(&As[k][ty * 8]);
        ulonglong2 a01 = ar[0];
        ulonglong2 a23 = ar[1];
        unsigned long long ap[4] = {a01.x, a01.y, a23.x, a23.y};
#pragma unroll
        for (int r = 0; r < 4; r++)
#pragma unroll
            for (int c = 0; c < 4; c++)
                acc2[r][c] = ffma2(ap[r], bp[c], acc2[r][c]);
    }

#pragma unroll
    for (int r = 0; r < 4; r++) {
        int ge = row0 + ty * 8 + 2 * r;
        float2 c0 = *reinterpret_cast<float2*>(&acc2[r][0]);
        float2 c1 = *reinterpret_cast<float2*>(&acc2[r][1]);
        float2 c2 = *reinterpret_cast<float2*>(&acc2[r][2]);
        float2 c3 = *reinterpret_cast<float2*>(&acc2[r][3]);
        if (ge < n) {
            float4 o = make_float4(c0.x, c1.x, c2.x, c3.x);
            *reinterpret_cast<float4*>(g_ys2 + (size_t)ge * HID + tx * 4) = o;
        }
        if (ge + 1 < n) {
            float4 o = make_float4(c0.y, c1.y, c2.y, c3.y);
            *reinterpret_cast<float4*>(g_ys2 + (size_t)(ge + 1) * HID + tx * 4) = o;
        }
    }
}

// ---------- FUSED: aggr(ys2) -> relu(+b1) -> dot W2 -> s1 = dinv * dot ----------
__global__ void k_fused_b(const float* __restrict__ b1,
                          const float* __restrict__ W2, int n) {
    int t = blockIdx.x * blockDim.x + threadIdx.x;
    int node = t >> 4;
    if (node >= n) return;
    int part = t & 15;

    float4 a = aggr_part(g_ys2, node, part);
    float4 b = __ldg(reinterpret_cast<const float4*>(b1 + part * 4));
    float4 w = __ldg(reinterpret_cast<const float4*>(W2 + part * 4));
    float s = fmaxf(a.x + b.x, 0.0f) * w.x
            + fmaxf(a.y + b.y, 0.0f) * w.y
            + fmaxf(a.z + b.z, 0.0f) * w.z
            + fmaxf(a.w + b.w, 0.0f) * w.w;
#pragma unroll
    for (int d = 8; d > 0; d >>= 1)
        s += __shfl_down_sync(0xffffffffu, s, d, 16);
    if (part == 0) g_s1[node] = s * g_dinv[node];
}

// ---------- FUSED: scalar aggr(s1) -> +b2 -> MLP head -> out ----------
__global__ void k_fused_c(const float* __restrict__ b2,
                          const float* __restrict__ Wm1,
                          const float* __restrict__ bm1,
                          const float* __restrict__ Wm2,
                          const float* __restrict__ bm2,
                          float* __restrict__ out, int n) {
    int i = blockIdx.x * blockDim.x + threadIdx.x;
    if (i >= n) return;
    float s = g_s1[i];
    int j   = g_off[i];
    int end = g_off[i + 1];
    for (; j + 4 <= end; j += 4) {
        float v0 = g_s1[g_srcs[j + 0]];
        float v1 = g_s1[g_srcs[j + 1]];
        float v2 = g_s1[g_srcs[j + 2]];
        float v3 = g_s1[g_srcs[j + 3]];
        s += v0 + v1 + v2 + v3;
    }
    for (; j < end; j++) s += g_s1[g_srcs[j]];
    float h2 = fmaf(s, g_dinv[i], __ldg(b2));

    const float4* w1 = reinterpret_cast<const float4*>(Wm1);
    const float4* bb = reinterpret_cast<const float4*>(bm1);
    const float4* w2 = reinterpret_cast<const float4*>(Wm2);
    float o = __ldg(bm2);
#pragma unroll
    for (int j4 = 0; j4 < HID / 4; j4++) {
        float4 a = __ldg(&w1[j4]);
        float4 b = __ldg(&bb[j4]);
        float4 c = __ldg(&w2[j4]);
        o += fmaxf(fmaf(h2, a.x, b.x), 0.0f) * c.x;
        o += fmaxf(fmaf(h2, a.y, b.y), 0.0f) * c.y;
        o += fmaxf(fmaf(h2, a.z, b.z), 0.0f) * c.z;
        o += fmaxf(fmaf(h2, a.w, b.w), 0.0f) * c.w;
    }
    out[i] = o;
}

extern "C" void kernel_launch(void* const* d_in, const int* in_sizes, int n_in,
                              void* d_out, int out_size) {
    const float* x   = (const float*)d_in[0];
    const void*  ei  = d_in[1];
    const float* W0  = (const float*)d_in[2];
    const float* b0  = (const float*)d_in[3];
    const float* W1  = (const float*)d_in[4];
    const float* b1  = (const float*)d_in[5];
    const float* W2  = (const float*)d_in[6];
    const float* b2  = (const float*)d_in[7];
    const float* Wm1 = (const float*)d_in[8];
    const float* bm1 = (const float*)d_in[9];
    const float* Wm2 = (const float*)d_in[10];
    const float* bm2 = (const float*)d_in[11];
    float* out = (float*)d_out;

    int n = in_sizes[0] / FIN;   // 100000
    int e = in_sizes[1] / 2;     // 1200000
    int nb = (n + SCAN_TILE - 1) / SCAN_TILE;   // 391

    static cudaStream_t sB = nullptr;
    static cudaEvent_t evFork = nullptr, evJoin = nullptr;
    if (sB == nullptr) {
        cudaStreamCreateWithFlags(&sB, cudaStreamNonBlocking);
        cudaEventCreateWithFlags(&evFork, cudaEventDisableTiming);
        cudaEventCreateWithFlags(&evJoin, cudaEventDisableTiming);
    }

    int gemm_grid = (n + 127) / 128;
    int node16_grid = (n * 16 + 255) / 256;

    // ---- fork: GEMM0 (independent of graph structure) on sB ----
    cudaEventRecord(evFork, 0);
    cudaStreamWaitEvent(sB, evFork, 0);
    k_gemm<FIN><<<gemm_grid, 256, 0, sB>>>(x, W0, n);
    cudaEventRecord(evJoin, sB);

    // ---- CSR build on default stream (concurrent with GEMM0) ----
    k_zero_detect<<<(n + 255) / 256, 256>>>((const long long*)ei, e, n);
    k_count<<<(e + 255) / 256, 256>>>(ei, e);
    k_blocksum<<<nb, SCAN_TILE>>>(n);
    k_scanpart<<<1, 512>>>(nb, n);
    k_finaloff<<<nb, SCAN_TILE>>>(n);
    k_fill <<<(e + 255) / 256, 256>>>(ei, e);

    // ---- join ----
    cudaStreamWaitEvent(0, evJoin, 0);

    // fused layer chain
    k_fused_ag<<<gemm_grid, 256>>>(W1, b0, n);                   // aggr0 + relu + @W1
    k_fused_b <<<node16_grid, 256>>>(b1, W2, n);                 // aggr1 + relu + .W2
    k_fused_c <<<(n + 255) / 256, 256>>>(b2, Wm1, bm1, Wm2, bm2, out, n);
}

// round 10
// speedup vs baseline: 2.4169x; 1.0102x over previous
#include <cuda_runtime.h>
#include <cuda_bf16.h>
#include <cstdint>

#define NN  100000
#define EE  1200000
#define FIN 128
#define HID 64
#define SCAN_TILE 256
#define MAX_PARTS ((NN + SCAN_TILE - 1) / SCAN_TILE)   // 391

// Scratch (static __device__ arrays — no allocation allowed)
__device__ __align__(256) float g_ys [(size_t)NN * HID];   // layer-0 gemm output (gather source)
__device__ __align__(256) float g_ys2[(size_t)NN * HID];   // layer-1 gemm output (gather source)
__device__ __align__(256) float g_dinv[NN];
__device__ __align__(256) int   g_cnt[NN];
__device__ __align__(256) int   g_off[NN + 1];
__device__ __align__(256) int   g_cur[NN];
__device__ __align__(256) int   g_part[MAX_PARTS];
__device__ __align__(256) int   g_srcs[EE];                // dst-sorted source ids (CSR)
__device__ __align__(256) float g_s1[NN];                  // scalar layer source (pre-scaled by dinv)
__device__ int g_is64;

// ---------- f32x2 packed-FMA helpers ----------
__device__ __forceinline__ unsigned long long ffma2(unsigned long long a,
                                                    unsigned long long b,
                                                    unsigned long long c) {
    unsigned long long d;
    asm("fma.rn.f32x2 %0, %1, %2, %3;" : "=l"(d) : "l"(a), "l"(b), "l"(c));
    return d;
}
__device__ __forceinline__ unsigned long long dup2(float x) {
    unsigned long long d;
    unsigned int u = __float_as_uint(x);
    asm("mov.b64 %0, {%1, %1};" : "=l"(d) : "r"(u));
    return d;
}

__device__ __forceinline__ int edge_at(const void* ei, int is64, size_t idx) {
    if (is64) return (int)((const long long*)ei)[idx];
    return ((const int*)ei)[idx];
}

// ---------- zero + edge-dtype detection (merged) ----------
__global__ void k_zero_detect(const long long* ei, int e, int n) {
    int i = blockIdx.x * blockDim.x + threadIdx.x;
    if (i < n) g_cnt[i] = 0;
    if (blockIdx.x == 0 && threadIdx.x < 32) {
        int t = threadIdx.x;
        int m = e < 32 ? e : 32;
        int bad = 0;
        if (t < m) {
            long long v = ei[t];
            if (v < 0 || v >= NN) bad = 1;
        }
        unsigned int anybad = __ballot_sync(0xffffffffu, bad);
        if (t == 0) g_is64 = (anybad == 0u);
    }
}

// ---------- CSR build: histogram (2 edges/thread) ----------
__global__ void k_count(const void* ei, int e) {
    int i = blockIdx.x * blockDim.x + threadIdx.x;
    int is64 = g_is64;
    if (!(e & 1)) {                       // even e: vector path, 16B/8B aligned
        int i2 = i * 2;
        if (i2 >= e) return;
        int d0, d1;
        if (is64) {
            ulonglong2 v = reinterpret_cast<const ulonglong2*>(ei)[((size_t)e + i2) >> 1];
            d0 = (int)v.x; d1 = (int)v.y;
        } else {
            int2 v = reinterpret_cast<const int2*>(ei)[((size_t)e + i2) >> 1];
            d0 = v.x; d1 = v.y;
        }
        if (d0 == d1) {
            atomicAdd(&g_cnt[d0], 2);
        } else {
            atomicAdd(&g_cnt[d0], 1);
            atomicAdd(&g_cnt[d1], 1);
        }
    } else {                              // odd e: scalar fallback
        if (i >= e) return;
        int dst = edge_at(ei, is64, (size_t)e + i);
        atomicAdd(&g_cnt[dst], 1);
    }
}

__global__ __launch_bounds__(SCAN_TILE) void k_blocksum(int n) {
    __shared__ int wsum[SCAN_TILE / 32];
    int t = threadIdx.x;
    int i = blockIdx.x * SCAN_TILE + t;
    int v = (i < n) ? g_cnt[i] : 0;
#pragma unroll
    for (int d = 16; d > 0; d >>= 1) v += __shfl_down_sync(0xffffffffu, v, d);
    if ((t & 31) == 0) wsum[t >> 5] = v;
    __syncthreads();
    if (t < SCAN_TILE / 32) {
        int s = wsum[t];
#pragma unroll
        for (int d = (SCAN_TILE / 64); d > 0; d >>= 1)
            s += __shfl_down_sync(0xffu, s, d);
        if (t == 0) g_part[blockIdx.x] = s;
    }
}

// merged: per-block prefix over g_part (warp 0) + intra-block scan; emits off/cur/dinv
__global__ __launch_bounds__(SCAN_TILE) void k_finaloff(int nb, int n) {
    __shared__ int wexc[SCAN_TILE / 32];
    __shared__ int s_base;
    int t = threadIdx.x;

    if (t < 32) {                          // prefix of partials before this block
        int sum = 0;
        for (int i = t; i < blockIdx.x; i += 32) sum += g_part[i];
#pragma unroll
        for (int d = 16; d > 0; d >>= 1) sum += __shfl_down_sync(0xffffffffu, sum, d);
        if (t == 0) s_base = sum;
    }

    int i = blockIdx.x * SCAN_TILE + t;
    int c = (i < n) ? g_cnt[i] : 0;
    int lane = t & 31, warp = t >> 5;
    int inc = c;
#pragma unroll
    for (int d = 1; d < 32; d <<= 1) {
        int v = __shfl_up_sync(0xffffffffu, inc, d);
        if (lane >= d) inc += v;
    }
    if (lane == 31) wexc[warp] = inc;
    __syncthreads();
    if (t < SCAN_TILE / 32) {
        int v = wexc[t];
        int e2 = v;
#pragma unroll
        for (int d = 1; d < SCAN_TILE / 32; d <<= 1) {
            int u = __shfl_up_sync(0xffu, e2, d);
            if (t >= d) e2 += u;
        }
        wexc[t] = e2 - v;
    }
    __syncthreads();

    int off = s_base + wexc[warp] + (inc - c);
    if (i < n) {
        g_off[i] = off;
        g_cur[i] = off;
        g_dinv[i] = rsqrtf(1.0f + (float)c);
    }
    if (blockIdx.x == nb - 1 && t == SCAN_TILE - 1)
        g_off[n] = off + c;
}

// ---------- fill (2 edges/thread) ----------
__global__ void k_fill(const void* ei, int e) {
    int i = blockIdx.x * blockDim.x + threadIdx.x;
    int is64 = g_is64;
    if (!(e & 1)) {
        int i2 = i * 2;
        if (i2 >= e) return;
        int s0, s1, d0, d1;
        if (is64) {
            ulonglong2 sv = reinterpret_cast<const ulonglong2*>(ei)[(size_t)i2 >> 1];
            ulonglong2 dv = reinterpret_cast<const ulonglong2*>(ei)[((size_t)e + i2) >> 1];
            s0 = (int)sv.x; s1 = (int)sv.y;
            d0 = (int)dv.x; d1 = (int)dv.y;
        } else {
            int2 sv = reinterpret_cast<const int2*>(ei)[(size_t)i2 >> 1];
            int2 dv = reinterpret_cast<const int2*>(ei)[((size_t)e + i2) >> 1];
            s0 = sv.x; s1 = sv.y;
            d0 = dv.x; d1 = dv.y;
        }
        if (d0 == d1) {
            int pos = atomicAdd(&g_cur[d0], 2);
            g_srcs[pos] = s0;
            g_srcs[pos + 1] = s1;
        } else {
            g_srcs[atomicAdd(&g_cur[d0], 1)] = s0;
            g_srcs[atomicAdd(&g_cur[d1], 1)] = s1;
        }
    } else {
        if (i >= e) return;
        int src = edge_at(ei, is64, (size_t)i);
        int dst = edge_at(ei, is64, (size_t)e + i);
        g_srcs[atomicAdd(&g_cur[dst], 1)] = src;
    }
}

// ---------- normalized pull of one node-part: acc = dv*(dv*self + sum du*nb) ----------
__device__ __forceinline__ float4 aggr_part(const float* __restrict__ src,
                                            int node, int part) {
    float dv = g_dinv[node];
    float4 self = *reinterpret_cast<const float4*>(src + (size_t)node * HID + part * 4);
    float4 acc;
    acc.x = self.x * dv; acc.y = self.y * dv;
    acc.z = self.z * dv; acc.w = self.w * dv;

    int j   = g_off[node];
    int end = g_off[node + 1];
    for (; j + 4 <= end; j += 4) {
        int s0 = g_srcs[j + 0], s1 = g_srcs[j + 1];
        int s2 = g_srcs[j + 2], s3 = g_srcs[j + 3];
        float d0 = g_dinv[s0], d1 = g_dinv[s1], d2 = g_dinv[s2], d3 = g_dinv[s3];
        float4 v0 = *reinterpret_cast<const float4*>(src + (size_t)s0 * HID + part * 4);
        float4 v1 = *reinterpret_cast<const float4*>(src + (size_t)s1 * HID + part * 4);
        float4 v2 = *reinterpret_cast<const float4*>(src + (size_t)s2 * HID + part * 4);
        float4 v3 = *reinterpret_cast<const float4*>(src + (size_t)s3 * HID + part * 4);
        acc.x = fmaf(d0, v0.x, fmaf(d1, v1.x, fmaf(d2, v2.x, fmaf(d3, v3.x, acc.x))));
        acc.y = fmaf(d0, v0.y, fmaf(d1, v1.y, fmaf(d2, v2.y, fmaf(d3, v3.y, acc.y))));
        acc.z = fmaf(d0, v0.z, fmaf(d1, v1.z, fmaf(d2, v2.z, fmaf(d3, v3.z, acc.z))));
        acc.w = fmaf(d0, v0.w, fmaf(d1, v1.w, fmaf(d2, v2.w, fmaf(d3, v3.w, acc.w))));
    }
    for (; j < end; j++) {
        int s = g_srcs[j];
        float du = g_dinv[s];
        float4 v = *reinterpret_cast<const float4*>(src + (size_t)s * HID + part * 4);
        acc.x = fmaf(du, v.x, acc.x); acc.y = fmaf(du, v.y, acc.y);
        acc.z = fmaf(du, v.z, acc.z); acc.w = fmaf(du, v.w, acc.w);
    }
    acc.x *= dv; acc.y *= dv; acc.z *= dv; acc.w *= dv;
    return acc;
}

// ---------- tiled SGEMM (f32x2 packed): ys = A @ W  (layer 0, K=128) ----------
template <int K>
__global__ __launch_bounds__(256)
void k_gemm(const float* __restrict__ A, const float* __restrict__ W, int n) {
    constexpr int BM = 128, BN = 64, BK = 16;
    __shared__ float Ws[K * BN];
    __shared__ float As[BK][BM];

    int tid = threadIdx.x;
    for (int i = tid; i < (K * BN) / 4; i += 256)
        reinterpret_cast<float4*>(Ws)[i] = reinterpret_cast<const float4*>(W)[i];

    int tx = tid & 15;
    int ty = tid >> 4;
    int row0 = blockIdx.x * BM;

    unsigned long long acc2[4][4];
#pragma unroll
    for (int r = 0; r < 4; r++)
#pragma unroll
        for (int c = 0; c < 4; c++) acc2[r][c] = 0ULL;

    for (int k0 = 0; k0 < K; k0 += BK) {
        __syncthreads();
#pragma unroll
        for (int l = 0; l < 2; l++) {
            int lin = tid + l * 256;
            int row = lin & 127;
            int kq  = lin >> 7;
            int grow = row0 + row;
            float4 v = make_float4(0.f, 0.f, 0.f, 0.f);
            if (grow < n)
                v = *reinterpret_cast<const float4*>(A + (size_t)grow * K + k0 + kq * 4);
            As[kq * 4 + 0][row] = v.x;
            As[kq * 4 + 1][row] = v.y;
            As[kq * 4 + 2][row] = v.z;
            As[kq * 4 + 3][row] = v.w;
        }
        __syncthreads();

#pragma unroll
        for (int k = 0; k < BK; k++) {
            float4 b = *reinterpret_cast<const float4*>(&Ws[(k0 + k) * BN + tx * 4]);
            unsigned long long bp[4] = {dup2(b.x), dup2(b.y), dup2(b.z), dup2(b.w)};
            const ulonglong2* ar = reinterpret_cast<const ulonglong2*>(&As[k][ty * 8]);
            ulonglong2 a01 = ar[0];
            ulonglong2 a23 = ar[1];
            unsigned long long ap[4] = {a01.x, a01.y, a23.x, a23.y};
#pragma unroll
            for (int r = 0; r < 4; r++)
#pragma unroll
                for (int c = 0; c < 4; c++)
                    acc2[r][c] = ffma2(ap[r], bp[c], acc2[r][c]);
        }
    }

#pragma unroll
    for (int r = 0; r < 4; r++) {
        int ge = row0 + ty * 8 + 2 * r;
        float2 c0 = *reinterpret_cast<float2*>(&acc2[r][0]);
        float2 c1 = *reinterpret_cast<float2*>(&acc2[r][1]);
        float2 c2 = *reinterpret_cast<float2*>(&acc2[r][2]);
        float2 c3 = *reinterpret_cast<float2*>(&acc2[r][3]);
        if (ge < n) {
            float4 o = make_float4(c0.x, c1.x, c2.x, c3.x);
            *reinterpret_cast<float4*>(g_ys + (size_t)ge * HID + tx * 4) = o;
        }
        if (ge + 1 < n) {
            float4 o = make_float4(c0.y, c1.y, c2.y, c3.y);
            *reinterpret_cast<float4*>(g_ys + (size_t)(ge + 1) * HID + tx * 4) = o;
        }
    }
}

// ---------- FUSED: aggr(ys) -> relu(+b0) -> @W1 -> ys2   (K=HID=64) ----------
__global__ __launch_bounds__(256)
void k_fused_ag(const float* __restrict__ W, const float* __restrict__ bias, int n) {
    constexpr int BM = 128, BN = 64, K = 64, AST = 132;
    __shared__ float Ws[K * BN];          // 16 KB
    __shared__ float As[K][AST];          // 33.8 KB, k-major transposed A tile

    int tid = threadIdx.x;
    for (int i = tid; i < (K * BN) / 4; i += 256)
        reinterpret_cast<float4*>(Ws)[i] = reinterpret_cast<const float4*>(W)[i];

    int row0 = blockIdx.x * BM;
    int part = tid & 15;      // feature part: 4 floats
    int grp  = tid >> 4;      // node group within pass

    float4 bk = *reinterpret_cast<const float4*>(bias + part * 4);

    // aggregation phase: 8 passes x 16 nodes
#pragma unroll 1
    for (int p = 0; p < 8; p++) {
        int nl = p * 16 + grp;
        int node = row0 + nl;
        float4 a = make_float4(0.f, 0.f, 0.f, 0.f);
        if (node < n) {
            a = aggr_part(g_ys, node, part);
            a.x = fmaxf(a.x + bk.x, 0.0f);
            a.y = fmaxf(a.y + bk.y, 0.0f);
            a.z = fmaxf(a.z + bk.z, 0.0f);
            a.w = fmaxf(a.w + bk.w, 0.0f);
        }
        As[part * 4 + 0][nl] = a.x;
        As[part * 4 + 1][nl] = a.y;
        As[part * 4 + 2][nl] = a.z;
        As[part * 4 + 3][nl] = a.w;
    }
    __syncthreads();

    // GEMM phase
    int tx = tid & 15;
    int ty = tid >> 4;
    unsigned long long acc2[4][4];
#pragma unroll
    for (int r = 0; r < 4; r++)
#pragma unroll
        for (int c = 0; c < 4; c++) acc2[r][c] = 0ULL;

#pragma unroll 8
    for (int k = 0; k < K; k++) {
        float4 b = *reinterpret_cast<const float4*>(&Ws[k * BN + tx * 4]);
        unsigned long long bp[4] = {dup2(b.x), dup2(b.y), dup2(b.z), dup2(b.w)};
        const ulonglong2* ar = reinterpret_cast<const ulonglong2*>(&As[k][ty * 8]);
        ulonglong2 a01 = ar[0];
        ulonglong2 a23 = ar[1];
        unsigned long long ap[4] = {a01.x, a01.y, a23.x, a23.y};
#pragma unroll
        for (int r = 0; r < 4; r++)
#pragma unroll
            for (int c = 0; c < 4; c++)
                acc2[r][c] = ffma2(ap[r], bp[c], acc2[r][c]);
    }

#pragma unroll
    for (int r = 0; r < 4; r++) {
        int ge = row0 + ty * 8 + 2 * r;
        float2 c0 = *reinterpret_cast<float2*>(&acc2[r][0]);
        float2 c1 = *reinterpret_cast<float2*>(&acc2[r][1]);
        float2 c2 = *reinterpret_cast<float2*>(&acc2[r][2]);
        float2 c3 = *reinterpret_cast<float2*>(&acc2[r][3]);
        if (ge < n) {
            float4 o = make_float4(c0.x, c1.x, c2.x, c3.x);
            *reinterpret_cast<float4*>(g_ys2 + (size_t)ge * HID + tx * 4) = o;
        }
        if (ge + 1 < n) {
            float4 o = make_float4(c0.y, c1.y, c2.y, c3.y);
            *reinterpret_cast<float4*>(g_ys2 + (size_t)(ge + 1) * HID + tx * 4) = o;
        }
    }
}

// ---------- FUSED: aggr(ys2) -> relu(+b1) -> dot W2 -> s1 = dinv * dot ----------
__global__ void k_fused_b(const float* __restrict__ b1,
                          const float* __restrict__ W2, int n) {
    int t = blockIdx.x * blockDim.x + threadIdx.x;
    int node = t >> 4;
    if (node >= n) return;
    int part = t & 15;

    float4 a = aggr_part(g_ys2, node, part);
    float4 b = __ldg(reinterpret_cast<const float4*>(b1 + part * 4));
    float4 w = __ldg(reinterpret_cast<const float4*>(W2 + part * 4));
    float s = fmaxf(a.x + b.x, 0.0f) * w.x
            + fmaxf(a.y + b.y, 0.0f) * w.y
            + fmaxf(a.z + b.z, 0.0f) * w.z
            + fmaxf(a.w + b.w, 0.0f) * w.w;
#pragma unroll
    for (int d = 8; d > 0; d >>= 1)
        s += __shfl_down_sync(0xffffffffu, s, d, 16);
    if (part == 0) g_s1[node] = s * g_dinv[node];
}

// ---------- FUSED: scalar aggr(s1) -> +b2 -> MLP head -> out ----------
__global__ void k_fused_c(const float* __restrict__ b2,
                          const float* __restrict__ Wm1,
                          const float* __restrict__ bm1,
                          const float* __restrict__ Wm2,
                          const float* __restrict__ bm2,
                          float* __restrict__ out, int n) {
    int i = blockIdx.x * blockDim.x + threadIdx.x;
    if (i >= n) return;
    float s = g_s1[i];
    int j   = g_off[i];
    int end = g_off[i + 1];
    for (; j + 4 <= end; j += 4) {
        float v0 = g_s1[g_srcs[j + 0]];
        float v1 = g_s1[g_srcs[j + 1]];
        float v2 = g_s1[g_srcs[j + 2]];
        float v3 = g_s1[g_srcs[j + 3]];
        s += v0 + v1 + v2 + v3;
    }
    for (; j < end; j++) s += g_s1[g_srcs[j]];
    float h2 = fmaf(s, g_dinv[i], __ldg(b2));

    const float4* w1 = reinterpret_cast<const float4*>(Wm1);
    const float4* bb = reinterpret_cast<const float4*>(bm1);
    const float4* w2 = reinterpret_cast<const float4*>(Wm2);
    float o = __ldg(bm2);
#pragma unroll
    for (int j4 = 0; j4 < HID / 4; j4++) {
        float4 a = __ldg(&w1[j4]);
        float4 b = __ldg(&bb[j4]);
        float4 c = __ldg(&w2[j4]);
        o += fmaxf(fmaf(h2, a.x, b.x), 0.0f) * c.x;
        o += fmaxf(fmaf(h2, a.y, b.y), 0.0f) * c.y;
        o += fmaxf(fmaf(h2, a.z, b.z), 0.0f) * c.z;
        o += fmaxf(fmaf(h2, a.w, b.w), 0.0f) * c.w;
    }
    out[i] = o;
}

extern "C" void kernel_launch(void* const* d_in, const int* in_sizes, int n_in,
                              void* d_out, int out_size) {
    const float* x   = (const float*)d_in[0];
    const void*  ei  = d_in[1];
    const float* W0  = (const float*)d_in[2];
    const float* b0  = (const float*)d_in[3];
    const float* W1  = (const float*)d_in[4];
    const float* b1  = (const float*)d_in[5];
    const float* W2  = (const float*)d_in[6];
    const float* b2  = (const float*)d_in[7];
    const float* Wm1 = (const float*)d_in[8];
    const float* bm1 = (const float*)d_in[9];
    const float* Wm2 = (const float*)d_in[10];
    const float* bm2 = (const float*)d_in[11];
    float* out = (float*)d_out;

    int n = in_sizes[0] / FIN;   // 100000
    int e = in_sizes[1] / 2;     // 1200000
    int nb = (n + SCAN_TILE - 1) / SCAN_TILE;   // 391

    static cudaStream_t sB = nullptr;
    static cudaEvent_t evFork = nullptr, evJoin = nullptr;
    if (sB == nullptr) {
        cudaStreamCreateWithFlags(&sB, cudaStreamNonBlocking);
        cudaEventCreateWithFlags(&evFork, cudaEventDisableTiming);
        cudaEventCreateWithFlags(&evJoin, cudaEventDisableTiming);
    }

    int gemm_grid = (n + 127) / 128;
    int node16_grid = (n * 16 + 255) / 256;
    int epair = (e & 1) ? e : e / 2;            // threads for 2-edge kernels

    // ---- fork: GEMM0 (independent of graph structure) on sB ----
    cudaEventRecord(evFork, 0);
    cudaStreamWaitEvent(sB, evFork, 0);
    k_gemm<FIN><<<gemm_grid, 256, 0, sB>>>(x, W0, n);
    cudaEventRecord(evJoin, sB);

    // ---- CSR build on default stream (concurrent with GEMM0) ----
    k_zero_detect<<<(n + 255) / 256, 256>>>((const long long*)ei, e, n);
    k_count<<<(epair + 255) / 256, 256>>>(ei, e);
    k_blocksum<<<nb, SCAN_TILE>>>(n);
    k_finaloff<<<nb, SCAN_TILE>>>(nb, n);
    k_fill <<<(epair + 255) / 256, 256>>>(ei, e);

    // ---- join ----
    cudaStreamWaitEvent(0, evJoin, 0);

    // fused layer chain
    k_fused_ag<<<gemm_grid, 256>>>(W1, b0, n);                   // aggr0 + relu + @W1
    k_fused_b <<<node16_grid, 256>>>(b1, W2, n);                 // aggr1 + relu + .W2
    k_fused_c <<<(n + 255) / 256, 256>>>(b2, Wm1, bm1, Wm2, bm2, out, n);
}